// round 10
// baseline (speedup 1.0000x reference)
#include <cuda_runtime.h>

// LayerNormSoftmaxChain: x[N,4] -> LN(4) -> @W[4,3] -> softmax(3) -> out[N,3]
// N = 8388608. HBM-streaming: 16B in / 12B out per row (224 MiB total).
//
// R9: persistent kernel, NO smem, NO barriers.
//  - R8's barriers + smem staging serialized every warp twice per tile and
//    left ~400cyc of exposed load latency per iteration (issue stuck at 42%).
//  - output written directly as 3 scalar STG.32 per row: a warp's stores at
//    12B lane-stride cover a CONTIGUOUS 384B segment per (warp,row-group) ->
//    3 lines/request (minimal wavefronts), L2 write-combines full sectors.
//  - warps fully independent: loads of tile k+1 issue right after stores of
//    tile k; 12 warps/SMSP rotate through the DRAM latency.
//  - param fold (10 floats) once per block, amortized over ~9 tiles.
//
// Algebra (verified rel_err 2.2e-7 since R6):
//   B[i][j] = gamma[i]*(W[i][j+1]-W[i][0]) ; B' = B - colmean(B)
//   l_j = inv * (x . B'_j) + c_j ,  c_j = sum_i beta[i]*(W[i][j+1]-W[i][0])
//   out = {1, e^l0, e^l1} / (1 + e^l0 + e^l1)

#define ROWS_PER_TILE 1024   // 256 threads * 4 rows

__global__ __launch_bounds__(256, 6)
void lnsm_kernel(const float4* __restrict__ x4,
                 const float* __restrict__ W,
                 const float* __restrict__ gamma,
                 const float* __restrict__ beta,
                 float* __restrict__ out,
                 int ntiles)
{
    const int t = threadIdx.x;

    // ---- param fold: once per block ----
    float B0[4], B1[4];
    float c0 = 0.f, c1 = 0.f;
    #pragma unroll
    for (int i = 0; i < 4; i++) {
        float g  = __ldg(gamma + i);
        float b  = __ldg(beta + i);
        float w0 = __ldg(W + i * 3 + 0);
        float w1 = __ldg(W + i * 3 + 1);
        float w2 = __ldg(W + i * 3 + 2);
        float d1 = w1 - w0, d2 = w2 - w0;
        B0[i] = g * d1;
        B1[i] = g * d2;
        c0 = fmaf(b, d1, c0);
        c1 = fmaf(b, d2, c1);
    }
    float m0 = (B0[0] + B0[1] + B0[2] + B0[3]) * 0.25f;
    float m1 = (B1[0] + B1[1] + B1[2] + B1[3]) * 0.25f;
    #pragma unroll
    for (int i = 0; i < 4; i++) { B0[i] -= m0; B1[i] -= m1; }

    for (int tile = blockIdx.x; tile < ntiles; tile += gridDim.x) {
        const float4* xb = x4 + (size_t)tile * ROWS_PER_TILE;

        // Front-batched coalesced streaming loads (MLP=4).
        float4 vs[4];
        vs[0] = __ldcs(xb + t);
        vs[1] = __ldcs(xb + t + 256);
        vs[2] = __ldcs(xb + t + 512);
        vs[3] = __ldcs(xb + t + 768);

        float* ob = out + (size_t)tile * (ROWS_PER_TILE * 3);

        #pragma unroll
        for (int r = 0; r < 4; r++) {
            float4 v = vs[r];

            float sum = (v.x + v.y) + (v.z + v.w);
            float mu  = sum * 0.25f;
            float sq  = fmaf(v.x, v.x, fmaf(v.y, v.y, fmaf(v.z, v.z, v.w * v.w)));
            float var = fmaf(sq, 0.25f, -mu * mu);
            float inv = rsqrtf(var + 1e-5f);

            float d0 = fmaf(v.x, B0[0], fmaf(v.y, B0[1], fmaf(v.z, B0[2], v.w * B0[3])));
            float d1 = fmaf(v.x, B1[0], fmaf(v.y, B1[1], fmaf(v.z, B1[2], v.w * B1[3])));

            float l0 = fmaf(inv, d0, c0);
            float l1 = fmaf(inv, d1, c1);

            // softmax with logit-0 shift: lane0's exp is exactly 1
            float e0 = __expf(l0);
            float e1 = __expf(l1);
            float rs = __fdividef(1.0f, 1.0f + e0 + e1);

            // Direct scalar streaming stores: warp covers contiguous 384B.
            int row = t + 256 * r;
            __stcs(ob + (size_t)row * 3 + 0, rs);
            __stcs(ob + (size_t)row * 3 + 1, e0 * rs);
            __stcs(ob + (size_t)row * 3 + 2, e1 * rs);
        }
    }
}

extern "C" void kernel_launch(void* const* d_in, const int* in_sizes, int n_in,
                              void* d_out, int out_size)
{
    const float* x     = (const float*)d_in[0];   // [N,4]
    const float* W     = (const float*)d_in[1];   // [4,3]
    const float* gamma = (const float*)d_in[2];   // [4]
    const float* beta  = (const float*)d_in[3];   // [4]
    float* out = (float*)d_out;                   // [N,3]

    int n_rows = in_sizes[0] / 4;
    int ntiles = n_rows / ROWS_PER_TILE;          // 8192

    static int sms = 0;
    if (sms == 0) cudaDeviceGetAttribute(&sms, cudaDevAttrMultiProcessorCount, 0);
    int blocks = sms * 6;                         // persistent: 6 blocks/SM
    if (blocks > ntiles) blocks = ntiles;

    lnsm_kernel<<<blocks, 256>>>((const float4*)x, W, gamma, beta, out, ntiles);
}

// round 11
// speedup vs baseline: 1.0679x; 1.0679x over previous
#include <cuda_runtime.h>

// LayerNormSoftmaxChain: x[N,4] -> LN(4) -> @W[4,3] -> softmax(3) -> out[N,3]
// N = 8388608. HBM-streaming: 16B in / 12B out per row (224 MiB total).
//
// R10: R2 (best kernel: 30.8us, DRAM 74%, occ 90%) had its params in
// __constant__ -> zero register cost, no per-block fold prologue. It lost
// only on wall via THREE memcpy graph nodes. Here: one tiny prep kernel
// folds gamma/beta/W into 10 floats in a __device__ scratch, then ONE 48B
// cudaMemcpyToSymbolAsync (D2D) fills the constant bank. Main kernel is
// R2's exact structure with the leaner R6 algebra (2 dots + 2 exps/row).
//
// Algebra (verified rel_err 2.2e-7 since R6):
//   B[i][j] = gamma[i]*(W[i][j+1]-W[i][0]) ; B' = B - colmean(B)
//   l_j = inv * (x . B'_j) + c_j ,  c_j = sum_i beta[i]*(W[i][j+1]-W[i][0])
//   out = {1, e^l0, e^l1} / (1 + e^l0 + e^l1)

__device__    float gScratch[12];
__constant__  float cP[12];   // [0..3]=B0, [4..7]=B1, [8]=c0, [9]=c1

__global__ void lnsm_prep(const float* __restrict__ W,
                          const float* __restrict__ gamma,
                          const float* __restrict__ beta)
{
    if (threadIdx.x == 0) {
        float B0[4], B1[4];
        float c0 = 0.f, c1 = 0.f;
        #pragma unroll
        for (int i = 0; i < 4; i++) {
            float g  = gamma[i];
            float b  = beta[i];
            float w0 = W[i * 3 + 0];
            float d1 = W[i * 3 + 1] - w0;
            float d2 = W[i * 3 + 2] - w0;
            B0[i] = g * d1;
            B1[i] = g * d2;
            c0 = fmaf(b, d1, c0);
            c1 = fmaf(b, d2, c1);
        }
        float m0 = (B0[0] + B0[1] + B0[2] + B0[3]) * 0.25f;
        float m1 = (B1[0] + B1[1] + B1[2] + B1[3]) * 0.25f;
        #pragma unroll
        for (int i = 0; i < 4; i++) {
            gScratch[i]     = B0[i] - m0;
            gScratch[4 + i] = B1[i] - m1;
        }
        gScratch[8] = c0;
        gScratch[9] = c1;
        gScratch[10] = 0.f;
        gScratch[11] = 0.f;
    }
}

#define ROWS_PER_BLOCK 1024   // 256 threads * 4 rows

__global__ __launch_bounds__(256, 6)
void lnsm_kernel(const float4* __restrict__ x4,
                 float4* __restrict__ out4)
{
    __shared__ float s[ROWS_PER_BLOCK * 3];   // 12 KB

    const int t = threadIdx.x;
    const float4* xb = x4 + (size_t)blockIdx.x * ROWS_PER_BLOCK;

    // Front-batch 4 coalesced LDG.128 (MLP=4).
    float4 v0 = xb[t];
    float4 v1 = xb[t + 256];
    float4 v2 = xb[t + 512];
    float4 v3 = xb[t + 768];

    float4 vs[4] = {v0, v1, v2, v3};

    #pragma unroll
    for (int r = 0; r < 4; r++) {
        float4 v = vs[r];

        float sum = (v.x + v.y) + (v.z + v.w);
        float mu  = sum * 0.25f;
        float sq  = fmaf(v.x, v.x, fmaf(v.y, v.y, fmaf(v.z, v.z, v.w * v.w)));
        float var = fmaf(sq, 0.25f, -mu * mu);
        float inv = rsqrtf(var + 1e-5f);

        // cbank operands: zero register cost
        float d0 = fmaf(v.x, cP[0], fmaf(v.y, cP[1], fmaf(v.z, cP[2], v.w * cP[3])));
        float d1 = fmaf(v.x, cP[4], fmaf(v.y, cP[5], fmaf(v.z, cP[6], v.w * cP[7])));

        float l0 = fmaf(inv, d0, cP[8]);
        float l1 = fmaf(inv, d1, cP[9]);

        // softmax with logit-0 shift: lane0's exp is exactly 1
        float e0 = __expf(l0);
        float e1 = __expf(l1);
        float rs = __fdividef(1.0f, 1.0f + e0 + e1);

        int row = t + 256 * r;
        s[row * 3 + 0] = rs;         // stride-3: coprime with 32 banks
        s[row * 3 + 1] = e0 * rs;
        s[row * 3 + 2] = e1 * rs;
    }

    __syncthreads();

    // Flush 768 float4 per block, perfectly coalesced.
    float4* ob = out4 + (size_t)blockIdx.x * (ROWS_PER_BLOCK * 3 / 4);
    const float4* s4 = (const float4*)s;
    ob[t]       = s4[t];
    ob[t + 256] = s4[t + 256];
    ob[t + 512] = s4[t + 512];
}

extern "C" void kernel_launch(void* const* d_in, const int* in_sizes, int n_in,
                              void* d_out, int out_size)
{
    const float* x     = (const float*)d_in[0];   // [N,4]
    const float* W     = (const float*)d_in[1];   // [4,3]
    const float* gamma = (const float*)d_in[2];   // [4]
    const float* beta  = (const float*)d_in[3];   // [4]
    float* out = (float*)d_out;                   // [N,3]

    static void* scratchAddr = nullptr;
    if (!scratchAddr) cudaGetSymbolAddress(&scratchAddr, gScratch);

    lnsm_prep<<<1, 32>>>(W, gamma, beta);
    cudaMemcpyToSymbolAsync(cP, scratchAddr, 12 * sizeof(float), 0,
                            cudaMemcpyDeviceToDevice);

    int n_rows = in_sizes[0] / 4;
    int blocks = n_rows / ROWS_PER_BLOCK;         // 8192, exact
    lnsm_kernel<<<blocks, 256>>>((const float4*)x, (float4*)out);
}

// round 12
// speedup vs baseline: 1.1612x; 1.0874x over previous
#include <cuda_runtime.h>

// LayerNormSoftmaxChain: x[N,4] -> LN(4) -> @W[4,3] -> softmax(3) -> out[N,3]
// N = 8388608. HBM-streaming: 16B in / 12B out per row (224 MiB total).
//
// R11: SINGLE kernel node (memcpy nodes cost ~6.4us each per graph replay;
// R10's 31.1us kernel lost 12.7us of wall to prep+memcpy).
//  - params folded by thread 0 into SHARED memory, overlapped with the
//    front-batched data loads already in flight
//  - params read at point-of-use through a volatile pointer: ptxas cannot
//    hoist them into 10 long-lived registers (the R6/R7 failure mode),
//    keeping peak pressure at R2's ~31 regs -> 8 blocks/SM
//  - proven R2 structure: 4x coalesced LDG.128 (MLP=4), smem-staged
//    coalesced float4 stores
//
// Algebra (verified rel_err 2.2e-7 since R6):
//   B[i][j] = gamma[i]*(W[i][j+1]-W[i][0]) ; B' = B - colmean(B)
//   l_j = inv * (x . B'_j) + c_j ,  c_j = sum_i beta[i]*(W[i][j+1]-W[i][0])
//   out = {1, e^l0, e^l1} / (1 + e^l0 + e^l1)

#define ROWS_PER_BLOCK 1024   // 256 threads * 4 rows

__global__ __launch_bounds__(256, 8)
void lnsm_kernel(const float4* __restrict__ x4,
                 const float* __restrict__ W,
                 const float* __restrict__ gamma,
                 const float* __restrict__ beta,
                 float4* __restrict__ out4)
{
    __shared__ float s[ROWS_PER_BLOCK * 3];   // 12 KB output staging
    __shared__ float sp[12];                  // folded params

    const int t = threadIdx.x;
    const float4* xb = x4 + (size_t)blockIdx.x * ROWS_PER_BLOCK;

    // Front-batch 4 coalesced LDG.128 (MLP=4) before anything else.
    float4 v0 = xb[t];
    float4 v1 = xb[t + 256];
    float4 v2 = xb[t + 512];
    float4 v3 = xb[t + 768];

    // Thread 0 folds params while everyone's data loads are in flight.
    if (t == 0) {
        float B0[4], B1[4];
        float c0 = 0.f, c1 = 0.f;
        #pragma unroll
        for (int i = 0; i < 4; i++) {
            float g  = __ldg(gamma + i);
            float b  = __ldg(beta + i);
            float w0 = __ldg(W + i * 3 + 0);
            float d1 = __ldg(W + i * 3 + 1) - w0;
            float d2 = __ldg(W + i * 3 + 2) - w0;
            B0[i] = g * d1;
            B1[i] = g * d2;
            c0 = fmaf(b, d1, c0);
            c1 = fmaf(b, d2, c1);
        }
        float m0 = (B0[0] + B0[1] + B0[2] + B0[3]) * 0.25f;
        float m1 = (B1[0] + B1[1] + B1[2] + B1[3]) * 0.25f;
        #pragma unroll
        for (int i = 0; i < 4; i++) {
            sp[i]     = B0[i] - m0;
            sp[4 + i] = B1[i] - m1;
        }
        sp[8] = c0;
        sp[9] = c1;
    }
    __syncthreads();

    // volatile: forces LDS at point-of-use, no 10-register param residency.
    volatile const float* p = sp;

    float4 vs[4] = {v0, v1, v2, v3};

    #pragma unroll
    for (int r = 0; r < 4; r++) {
        float4 v = vs[r];

        float sum = (v.x + v.y) + (v.z + v.w);
        float mu  = sum * 0.25f;
        float sq  = fmaf(v.x, v.x, fmaf(v.y, v.y, fmaf(v.z, v.z, v.w * v.w)));
        float var = fmaf(sq, 0.25f, -mu * mu);
        float inv = rsqrtf(var + 1e-5f);

        float d0 = fmaf(v.x, p[0], fmaf(v.y, p[1], fmaf(v.z, p[2], v.w * p[3])));
        float d1 = fmaf(v.x, p[4], fmaf(v.y, p[5], fmaf(v.z, p[6], v.w * p[7])));

        float l0 = fmaf(inv, d0, p[8]);
        float l1 = fmaf(inv, d1, p[9]);

        // softmax with logit-0 shift: lane0's exp is exactly 1
        float e0 = __expf(l0);
        float e1 = __expf(l1);
        float rs = __fdividef(1.0f, 1.0f + e0 + e1);

        int row = t + 256 * r;
        s[row * 3 + 0] = rs;         // stride-3: coprime with 32 banks
        s[row * 3 + 1] = e0 * rs;
        s[row * 3 + 2] = e1 * rs;
    }

    __syncthreads();

    // Flush 768 float4 per block, perfectly coalesced.
    float4* ob = out4 + (size_t)blockIdx.x * (ROWS_PER_BLOCK * 3 / 4);
    const float4* s4 = (const float4*)s;
    ob[t]       = s4[t];
    ob[t + 256] = s4[t + 256];
    ob[t + 512] = s4[t + 512];
}

extern "C" void kernel_launch(void* const* d_in, const int* in_sizes, int n_in,
                              void* d_out, int out_size)
{
    const float* x     = (const float*)d_in[0];   // [N,4]
    const float* W     = (const float*)d_in[1];   // [4,3]
    const float* gamma = (const float*)d_in[2];   // [4]
    const float* beta  = (const float*)d_in[3];   // [4]
    float* out = (float*)d_out;                   // [N,3]

    int n_rows = in_sizes[0] / 4;
    int blocks = n_rows / ROWS_PER_BLOCK;         // 8192, exact
    lnsm_kernel<<<blocks, 256>>>((const float4*)x, W, gamma, beta, (float4*)out);
}

// round 14
// speedup vs baseline: 1.1877x; 1.0227x over previous
#include <cuda_runtime.h>
#include <cstdint>

// LayerNormSoftmaxChain: x[N,4] -> LN(4) -> @W[4,3] -> softmax(3) -> out[N,3]
// N = 8388608. HBM-streaming: 16B in / 12B out per row (224 MiB total).
//
// R14 = R12 with the compile fix: volatile float4 copy has no copy ctor, so
// the point-of-use param reads use inline PTX ld.volatile.shared.v4.f32
// (guaranteed LDS.128 at point of use, not hoistable into 8 resident regs).
//  - single kernel node (memcpy nodes cost ~3-6us each per graph replay)
//  - thread 0 folds params into smem, overlapped with in-flight data loads
//  - 2 broadcast LDS.128 per row iter (8 LDS/thread total, vs R11's 40)
//  - multiplicative consts E_j = exp(c_j): 2 hoisted regs
//  - launch_bounds(256,7): keeps 4x LDG.128 front-batched (MLP=4),
//    floor 7 blocks/SM
//
// Algebra (rel_err ~2e-7 verified since R6):
//   B[i][j] = gamma[i]*(W[i][j+1]-W[i][0]) ; B' = B - colmean(B)
//   d_j = x . B'_j ; e_j = E_j * exp(inv*d_j), E_j = exp(sum_i beta_i*(W_ij+1-W_i0))
//   out = {1, e0, e1} / (1 + e0 + e1)

#define ROWS_PER_BLOCK 1024   // 256 threads * 4 rows

__device__ __forceinline__ float4 lds128_volatile(uint32_t saddr) {
    float4 r;
    asm volatile("ld.volatile.shared.v4.f32 {%0, %1, %2, %3}, [%4];"
                 : "=f"(r.x), "=f"(r.y), "=f"(r.z), "=f"(r.w)
                 : "r"(saddr));
    return r;
}

__global__ __launch_bounds__(256, 7)
void lnsm_kernel(const float4* __restrict__ x4,
                 const float* __restrict__ W,
                 const float* __restrict__ gamma,
                 const float* __restrict__ beta,
                 float4* __restrict__ out4)
{
    __shared__ float s[ROWS_PER_BLOCK * 3];      // 12 KB output staging
    __shared__ __align__(16) float sp[12];       // B0[4], B1[4], E0, E1

    const int t = threadIdx.x;
    const float4* xb = x4 + (size_t)blockIdx.x * ROWS_PER_BLOCK;

    // Front-batch 4 coalesced LDG.128 (MLP=4) before anything else.
    float4 v0 = xb[t];
    float4 v1 = xb[t + 256];
    float4 v2 = xb[t + 512];
    float4 v3 = xb[t + 768];

    // Thread 0 folds params while all data loads are in flight.
    if (t == 0) {
        float B0[4], B1[4];
        float c0 = 0.f, c1 = 0.f;
        #pragma unroll
        for (int i = 0; i < 4; i++) {
            float g  = __ldg(gamma + i);
            float b  = __ldg(beta + i);
            float w0 = __ldg(W + i * 3 + 0);
            float d1 = __ldg(W + i * 3 + 1) - w0;
            float d2 = __ldg(W + i * 3 + 2) - w0;
            B0[i] = g * d1;
            B1[i] = g * d2;
            c0 = fmaf(b, d1, c0);
            c1 = fmaf(b, d2, c1);
        }
        float m0 = (B0[0] + B0[1] + B0[2] + B0[3]) * 0.25f;
        float m1 = (B1[0] + B1[1] + B1[2] + B1[3]) * 0.25f;
        #pragma unroll
        for (int i = 0; i < 4; i++) {
            sp[i]     = B0[i] - m0;
            sp[4 + i] = B1[i] - m1;
        }
        sp[8] = __expf(c0);
        sp[9] = __expf(c1);
    }
    __syncthreads();

    // E0/E1 hoisted into 2 registers; B re-read per iteration via LDS.128.
    float E0 = sp[8];
    float E1 = sp[9];
    uint32_t spAddr = (uint32_t)__cvta_generic_to_shared(sp);

    float4 vs[4] = {v0, v1, v2, v3};

    #pragma unroll
    for (int r = 0; r < 4; r++) {
        float4 v = vs[r];

        float sum = (v.x + v.y) + (v.z + v.w);
        float mu  = sum * 0.25f;
        float sq  = fmaf(v.x, v.x, fmaf(v.y, v.y, fmaf(v.z, v.z, v.w * v.w)));
        float var = fmaf(sq, 0.25f, -mu * mu);
        float inv = rsqrtf(var + 1e-5f);

        // 2 broadcast LDS.128 per iteration, not hoistable.
        float4 P = lds128_volatile(spAddr);
        float4 Q = lds128_volatile(spAddr + 16u);

        float d0 = fmaf(v.x, P.x, fmaf(v.y, P.y, fmaf(v.z, P.z, v.w * P.w)));
        float d1 = fmaf(v.x, Q.x, fmaf(v.y, Q.y, fmaf(v.z, Q.z, v.w * Q.w)));

        // softmax with logit-0 shift; additive consts folded multiplicatively
        float e0 = E0 * __expf(inv * d0);
        float e1 = E1 * __expf(inv * d1);
        float rs = __fdividef(1.0f, 1.0f + e0 + e1);

        int row = t + 256 * r;
        s[row * 3 + 0] = rs;         // stride-3: coprime with 32 banks
        s[row * 3 + 1] = e0 * rs;
        s[row * 3 + 2] = e1 * rs;
    }

    __syncthreads();

    // Flush 768 float4 per block, perfectly coalesced.
    float4* ob = out4 + (size_t)blockIdx.x * (ROWS_PER_BLOCK * 3 / 4);
    const float4* s4 = (const float4*)s;
    ob[t]       = s4[t];
    ob[t + 256] = s4[t + 256];
    ob[t + 512] = s4[t + 512];
}

extern "C" void kernel_launch(void* const* d_in, const int* in_sizes, int n_in,
                              void* d_out, int out_size)
{
    const float* x     = (const float*)d_in[0];   // [N,4]
    const float* W     = (const float*)d_in[1];   // [4,3]
    const float* gamma = (const float*)d_in[2];   // [4]
    const float* beta  = (const float*)d_in[3];   // [4]
    float* out = (float*)d_out;                   // [N,3]

    int n_rows = in_sizes[0] / 4;
    int blocks = n_rows / ROWS_PER_BLOCK;         // 8192, exact
    lnsm_kernel<<<blocks, 256>>>((const float4*)x, W, gamma, beta, (float4*)out);
}